// round 7
// baseline (speedup 1.0000x reference)
#include <cuda_runtime.h>
#include <cuda_bf16.h>

#define BATCH 8
#define CH    256
#define NPOS  4096
#define IDIM  32

typedef unsigned long long u64;
typedef unsigned int u32;

__device__ __forceinline__ u64 pack2(float lo, float hi) {
    u64 r; asm("mov.b64 %0, {%1, %2};" : "=l"(r) : "f"(lo), "f"(hi)); return r;
}
__device__ __forceinline__ u64 ffma2(u64 a, u64 b, u64 c) {
    u64 d; asm("fma.rn.f32x2 %0, %1, %2, %3;" : "=l"(d) : "l"(a), "l"(b), "l"(c)); return d;
}
__device__ __forceinline__ u64 fmul2(u64 a, u64 b) {
    u64 d; asm("mul.rn.f32x2 %0, %1, %2;" : "=l"(d) : "l"(a), "l"(b)); return d;
}
__device__ __forceinline__ u64 fadd2(u64 a, u64 b) {
    u64 d; asm("add.rn.f32x2 %0, %1, %2;" : "=l"(d) : "l"(a), "l"(b)); return d;
}
__device__ __forceinline__ float2 unpack2(u64 a) {
    float2 f; asm("mov.b64 {%0, %1}, %2;" : "=f"(f.x), "=f"(f.y) : "l"(a)); return f;
}
__device__ __forceinline__ u32 bf2(float lo, float hi) {
    u32 r; asm("cvt.rn.bf16x2.f32 %0, %1, %2;" : "=r"(r) : "f"(hi), "f"(lo)); return r;
}
__device__ __forceinline__ u32 smem_u32(const void* p) {
    u32 a; asm("{ .reg .u64 t; cvta.to.shared.u64 t, %1; cvt.u32.u64 %0, t; }" : "=r"(a) : "l"(p));
    return a;
}
__device__ __forceinline__ void mma16816(float* d, u32 a0, u32 a1, u32 a2, u32 a3,
                                         u32 b0, u32 b1) {
    asm volatile("mma.sync.aligned.m16n8k16.row.col.f32.bf16.bf16.f32 "
                 "{%0,%1,%2,%3}, {%4,%5,%6,%7}, {%8,%9}, {%0,%1,%2,%3};"
                 : "+f"(d[0]), "+f"(d[1]), "+f"(d[2]), "+f"(d[3])
                 : "r"(a0), "r"(a1), "r"(a2), "r"(a3), "r"(b0), "r"(b1));
}
__device__ __forceinline__ void cpa16(u32 dst, const void* src) {
    asm volatile("cp.async.ca.shared.global [%0], [%1], 16;" :: "r"(dst), "l"(src));
}
__device__ __forceinline__ void cpa_commit() { asm volatile("cp.async.commit_group;" ::: "memory"); }
__device__ __forceinline__ void cpa_wait0()  { asm volatile("cp.async.wait_group 0;" ::: "memory"); }
__device__ __forceinline__ void cpa_wait1()  { asm volatile("cp.async.wait_group 1;" ::: "memory"); }

// Fast exp on the FMA pipe (no MUFU)
__device__ __forceinline__ void exp_pair(float s0, float s1, float& p0, float& p1) {
    const float MAGIC = 12582912.f;   // 1.5 * 2^23
    u64 t2  = fmul2(pack2(s0, s1), pack2(1.4426950408889634f, 1.4426950408889634f));
    u64 r2  = fadd2(t2, pack2(MAGIC, MAGIC));
    u64 rm2 = fadd2(r2, pack2(-MAGIC, -MAGIC));
    u64 f2  = ffma2(rm2, pack2(-1.f, -1.f), t2);
    u64 q2  = ffma2(f2, pack2(1.3333558146e-3f, 1.3333558146e-3f),
                        pack2(9.6181291076e-3f, 9.6181291076e-3f));
    q2 = ffma2(f2, q2, pack2(5.5504108664e-2f, 5.5504108664e-2f));
    q2 = ffma2(f2, q2, pack2(2.4022650696e-1f, 2.4022650696e-1f));
    q2 = ffma2(f2, q2, pack2(6.9314718056e-1f, 6.9314718056e-1f));
    q2 = ffma2(f2, q2, pack2(1.f, 1.f));
    float2 rr = unpack2(r2);
    float2 qq = unpack2(q2);
    int e0 = (__float_as_int(rr.x) - 0x4B400000) << 23;
    int e1 = (__float_as_int(rr.y) - 0x4B400000) << 23;
    p0 = __int_as_float(__float_as_int(qq.x) + e0);
    p1 = __int_as_float(__float_as_int(qq.y) + e1);
}

// Scratch: split-bf16 Q/K transposed [b][pos][32 i]; V bf16 [b][c][n]
__device__ __nv_bfloat16 g_qhi[BATCH * NPOS * IDIM];
__device__ __nv_bfloat16 g_qlo[BATCH * NPOS * IDIM];
__device__ __nv_bfloat16 g_khi[BATCH * NPOS * IDIM];
__device__ __nv_bfloat16 g_klo[BATCH * NPOS * IDIM];
__device__ __nv_bfloat16 g_v  [BATCH * CH * NPOS];

__device__ __forceinline__ void split_store(__nv_bfloat16* Ah, __nv_bfloat16* Al,
                                            size_t base, float v) {
    __nv_bfloat16 h = __float2bfloat16(v);
    Ah[base] = h;
    Al[base] = __float2bfloat16(v - __bfloat162float(h));
}

// ---------------------------------------------------------------------------
// Kernel 1: fused QKV projections (q,k split-bf16 transposed; v bf16)
// ---------------------------------------------------------------------------
__global__ __launch_bounds__(256, 2)
void qkv_kernel(const float* __restrict__ x,
                const float* __restrict__ Wq, const float* __restrict__ bq,
                const float* __restrict__ Wk, const float* __restrict__ bk,
                const float* __restrict__ Wv, const float* __restrict__ bv)
{
    __shared__ float4 xs4[CH * 8];
    const int b   = blockIdx.y;
    const int n0  = blockIdx.x * 32;
    const int tid = threadIdx.x;

    for (int idx = tid; idx < CH * 8; idx += 256) {
        int c = idx >> 3, pq = idx & 7;
        xs4[idx] = *(const float4*)(x + (size_t)(b * CH + c) * NPOS + n0 + pq * 4);
    }
    __syncthreads();

    const int pq = tid & 7;
    const int rg = tid >> 3;

    #pragma unroll
    for (int a = 0; a < 2; a++) {
        const float* wp[5];
        int rows[5];
        u64 A01[5], A23[5];
        #pragma unroll
        for (int ss = 0; ss < 5; ss++) {
            int r = rg + 32 * (5 * a + ss);
            rows[ss] = r;
            float bias;
            if (r < 32)      { wp[ss] = Wq + r * CH;        bias = bq[r]; }
            else if (r < 64) { wp[ss] = Wk + (r - 32) * CH; bias = bk[r - 32]; }
            else             { wp[ss] = Wv + (r - 64) * CH; bias = bv[r - 64]; }
            A01[ss] = pack2(bias, bias);
            A23[ss] = pack2(0.f, 0.f);
        }
        for (int c = 0; c < CH; c += 4) {
            ulonglong2 xa = *(const ulonglong2*)&xs4[(c + 0) * 8 + pq];
            ulonglong2 xb = *(const ulonglong2*)&xs4[(c + 1) * 8 + pq];
            ulonglong2 xc = *(const ulonglong2*)&xs4[(c + 2) * 8 + pq];
            ulonglong2 xd = *(const ulonglong2*)&xs4[(c + 3) * 8 + pq];
            #pragma unroll
            for (int ss = 0; ss < 5; ss++) {
                float4 w = *(const float4*)(wp[ss] + c);
                u64 wx = pack2(w.x, w.x), wy = pack2(w.y, w.y);
                u64 wz = pack2(w.z, w.z), ww = pack2(w.w, w.w);
                A01[ss] = ffma2(wx, xa.x, A01[ss]);
                A23[ss] = ffma2(wx, xa.y, A23[ss]);
                A01[ss] = ffma2(wy, xb.x, A01[ss]);
                A23[ss] = ffma2(wy, xb.y, A23[ss]);
                A01[ss] = ffma2(wz, xc.x, A01[ss]);
                A23[ss] = ffma2(wz, xc.y, A23[ss]);
                A01[ss] = ffma2(ww, xd.x, A01[ss]);
                A23[ss] = ffma2(ww, xd.y, A23[ss]);
            }
        }
        #pragma unroll
        for (int ss = 0; ss < 5; ss++) {
            int r = rows[ss];
            float2 lo = unpack2(A01[ss]);
            float2 hi = unpack2(A23[ss]);
            float bias2;
            if (r < 32)      bias2 = bq[r];
            else if (r < 64) bias2 = bk[r - 32];
            else             bias2 = bv[r - 64];
            float v0 = lo.x, v1 = lo.y, v2 = hi.x + bias2, v3 = hi.y + bias2;
            int m = n0 + pq * 4;
            if (r < 32) {
                size_t base = ((size_t)b * NPOS + m) * IDIM + r;
                split_store(g_qhi, g_qlo, base,            v0);
                split_store(g_qhi, g_qlo, base + IDIM,     v1);
                split_store(g_qhi, g_qlo, base + 2 * IDIM, v2);
                split_store(g_qhi, g_qlo, base + 3 * IDIM, v3);
            } else if (r < 64) {
                size_t base = ((size_t)b * NPOS + m) * IDIM + (r - 32);
                split_store(g_khi, g_klo, base,            v0);
                split_store(g_khi, g_klo, base + IDIM,     v1);
                split_store(g_khi, g_klo, base + 2 * IDIM, v2);
                split_store(g_khi, g_klo, base + 3 * IDIM, v3);
            } else {
                __nv_bfloat16* op = g_v + (size_t)(b * CH + (r - 64)) * NPOS + m;
                *(uint2*)op = make_uint2(bf2(v0, v1), bf2(v2, v3));
            }
        }
    }
}

// ---------------------------------------------------------------------------
// Kernel 2: attention. M-tile 64, 256 threads (8 warps), chunk 64 keys.
// 2 CTAs per SM (smem ~76KB, regs 128) -> cross-CTA latency hiding.
// ---------------------------------------------------------------------------
#define LARR_OFF 0                      // [2][64] f32 = 512B
#define QHI_OFF  1024                   // [64 m][40 i] bf16 (80B pitch); lo = +5120
#define KB0_OFF  (QHI_OFF + 10240)      // K buf0: hi 5120 + lo 5120
#define KB1_OFF  (KB0_OFF + 10240)      // K buf1
#define P_OFF    (KB1_OFF + 10240)      // [64 m][72 n] bf16 (144B pitch) = 9216
#define V_OFF    (P_OFF + 9216)         // [256 c][72 n] bf16 (144B pitch) = 36864
#define SM_TOTAL (V_OFF + 36864)        // 77824 B

__global__ __launch_bounds__(256, 2)
void attn_kernel(const float* __restrict__ x,
                 const float* __restrict__ gamma,
                 float* __restrict__ out)
{
    extern __shared__ char sm[];
    float* larr = (float*)(sm + LARR_OFF);
    const u32 smb = smem_u32(sm);

    const int b    = blockIdx.y;
    const int m0   = blockIdx.x * 64;
    const int tid  = threadIdx.x;
    const int w    = tid >> 5;
    const int lane = tid & 31;
    const int g    = w >> 1;        // S: q-group (16 queries, 0..3)
    const int h    = w & 1;         // S: key half (32 keys)
    const int lr4  = lane >> 2;
    const int lc2  = (lane & 3) * 2;

    const __nv_bfloat16* qhb = g_qhi + ((size_t)b * NPOS + m0) * IDIM;
    const __nv_bfloat16* qlb = g_qlo + ((size_t)b * NPOS + m0) * IDIM;
    const __nv_bfloat16* khb = g_khi + (size_t)b * NPOS * IDIM;
    const __nv_bfloat16* klb = g_klo + (size_t)b * NPOS * IDIM;
    const __nv_bfloat16* vb  = g_v   + (size_t)b * CH * NPOS;

    // ---- Prologue: group0 = Q + K(0), group1 = V(0) ----
    #pragma unroll
    for (int it = 0; it < 2; it++) {
        int idx = tid + it * 256;                  // 512 ops: Q hi/lo
        int j = idx & 3, row = (idx >> 2) & 63, wh = idx >> 8;
        cpa16(smb + QHI_OFF + wh * 5120 + row * 80 + j * 16,
              (wh ? qlb : qhb) + row * IDIM + j * 8);
    }
    #pragma unroll
    for (int it = 0; it < 2; it++) {
        int idx = tid + it * 256;                  // 512 ops: K(0) hi/lo
        int j = idx & 3, row = (idx >> 2) & 63, wh = idx >> 8;
        cpa16(smb + KB0_OFF + wh * 5120 + row * 80 + j * 16,
              (wh ? klb : khb) + row * IDIM + j * 8);
    }
    cpa_commit();
    #pragma unroll
    for (int it = 0; it < 8; it++) {
        int idx = tid + it * 256;                  // 2048 ops: V(0) [256c x 64n]
        int c = idx >> 3, j = idx & 7;
        cpa16(smb + V_OFF + c * 144 + j * 16, vb + (size_t)c * NPOS + j * 8);
    }
    cpa_commit();

    float o[2][8][4];
    #pragma unroll
    for (int mi = 0; mi < 2; mi++)
        #pragma unroll
        for (int cj = 0; cj < 8; cj++)
            #pragma unroll
            for (int r = 0; r < 4; r++) o[mi][cj][r] = 0.f;
    u64 lrA2 = 0ull, lrB2 = 0ull;

    const int mb2 = (w & 1) * 32;      // PV: m-block
    const int cb0 = (w >> 1) * 64;     // PV: c-block

    for (int kk = 0; kk < NPOS / 64; kk++) {
        if (kk > 0) {
            __syncthreads();           // PV(kk-1) done -> V buffer free
            const int n0 = kk * 64;
            #pragma unroll
            for (int it = 0; it < 8; it++) {
                int idx = tid + it * 256;
                int c = idx >> 3, j = idx & 7;
                cpa16(smb + V_OFF + c * 144 + j * 16, vb + (size_t)c * NPOS + n0 + j * 8);
            }
            cpa_commit();
        }
        cpa_wait1();                   // K(kk) (+Q on kk=0) landed
        __syncthreads();

        const char* kh = sm + ((kk & 1) ? KB1_OFF : KB0_OFF);

        // ---- S phase: warp computes S[16q x 32n], split-bf16 (3 MMA/k-step) ----
        {
            u32 ah[2][4], al[2][4];
            #pragma unroll
            for (int ks = 0; ks < 2; ks++) {
                int kby = (ks * 16 + lc2) * 2;
                const char* pah = sm + QHI_OFF + (g * 16 + lr4) * 80 + kby;
                ah[ks][0] = *(const u32*)(pah);
                ah[ks][1] = *(const u32*)(pah + 8 * 80);
                ah[ks][2] = *(const u32*)(pah + 16);
                ah[ks][3] = *(const u32*)(pah + 8 * 80 + 16);
                al[ks][0] = *(const u32*)(pah + 5120);
                al[ks][1] = *(const u32*)(pah + 5120 + 8 * 80);
                al[ks][2] = *(const u32*)(pah + 5120 + 16);
                al[ks][3] = *(const u32*)(pah + 5120 + 8 * 80 + 16);
            }
            const int mA = g * 16 + lr4;
            #pragma unroll
            for (int nb = 0; nb < 4; nb++) {
                const int nbase = h * 32 + nb * 8;
                float d[4] = {0.f, 0.f, 0.f, 0.f};
                #pragma unroll
                for (int ks = 0; ks < 2; ks++) {
                    int kby = (ks * 16 + lc2) * 2;
                    const char* pbh = kh + (nbase + lr4) * 80 + kby;
                    u32 bh0 = *(const u32*)(pbh);
                    u32 bh1 = *(const u32*)(pbh + 16);
                    u32 bl0 = *(const u32*)(pbh + 5120);
                    u32 bl1 = *(const u32*)(pbh + 5120 + 16);
                    mma16816(d, ah[ks][0], ah[ks][1], ah[ks][2], ah[ks][3], bh0, bh1);
                    mma16816(d, ah[ks][0], ah[ks][1], ah[ks][2], ah[ks][3], bl0, bl1);
                    mma16816(d, al[ks][0], al[ks][1], al[ks][2], al[ks][3], bh0, bh1);
                }
                float pA0, pA1, pB0, pB1;
                exp_pair(d[0], d[1], pA0, pA1);
                exp_pair(d[2], d[3], pB0, pB1);
                lrA2 = fadd2(lrA2, pack2(pA0, pA1));
                lrB2 = fadd2(lrB2, pack2(pB0, pB1));
                const int c0 = nbase + lc2;
                *(u32*)(sm + P_OFF + mA * 144 + c0 * 2)       = bf2(pA0, pA1);
                *(u32*)(sm + P_OFF + (mA + 8) * 144 + c0 * 2) = bf2(pB0, pB1);
            }
        }
        __syncthreads();   // P ready; K(kk) fully consumed

        if (kk < NPOS / 64 - 1) {      // prefetch K(kk+1) behind PV
            const int n1 = (kk + 1) * 64;
            const u32 kdst = smb + (((kk + 1) & 1) ? KB1_OFF : KB0_OFF);
            #pragma unroll
            for (int it = 0; it < 2; it++) {
                int idx = tid + it * 256;
                int j = idx & 3, row = (idx >> 2) & 63, wh = idx >> 8;
                cpa16(kdst + wh * 5120 + row * 80 + j * 16,
                      (wh ? klb : khb) + (size_t)(n1 + row) * IDIM + j * 8);
            }
            cpa_commit();
            cpa_wait1();               // V(kk) landed (K(kk+1) may pend)
        } else {
            cpa_wait0();
        }
        __syncthreads();               // V visible to all

        // ---- PV phase: O[32m x 64c] += P * V^T (4 k-steps) ----
        #pragma unroll
        for (int kstep = 0; kstep < 4; kstep++) {
            const int kby = (kstep * 16 + lc2) * 2;
            u32 a[2][4];
            #pragma unroll
            for (int mi = 0; mi < 2; mi++) {
                const char* pa = sm + P_OFF + (mb2 + mi * 16 + lr4) * 144 + kby;
                a[mi][0] = *(const u32*)(pa);
                a[mi][1] = *(const u32*)(pa + 8 * 144);
                a[mi][2] = *(const u32*)(pa + 16);
                a[mi][3] = *(const u32*)(pa + 8 * 144 + 16);
            }
            #pragma unroll
            for (int cj = 0; cj < 8; cj++) {
                const char* pb = sm + V_OFF + (cb0 + cj * 8 + lr4) * 144 + kby;
                u32 b0 = *(const u32*)(pb);
                u32 b1 = *(const u32*)(pb + 16);
                mma16816(o[0][cj], a[0][0], a[0][1], a[0][2], a[0][3], b0, b1);
                mma16816(o[1][cj], a[1][0], a[1][1], a[1][2], a[1][3], b0, b1);
            }
        }
    }

    // ---- l reduction ----
    {
        float2 fa = unpack2(lrA2);
        float2 fb = unpack2(lrB2);
        float lA = fa.x + fa.y;
        float lB = fb.x + fb.y;
        #pragma unroll
        for (int off = 1; off <= 2; off <<= 1) {
            lA += __shfl_xor_sync(0xffffffffu, lA, off);
            lB += __shfl_xor_sync(0xffffffffu, lB, off);
        }
        if ((lane & 3) == 0) {
            larr[h * 64 + g * 16 + lr4]     = lA;
            larr[h * 64 + g * 16 + lr4 + 8] = lB;
        }
    }
    __syncthreads();

    // ---- Epilogue: out[b][c][m] = gamma/l * O + x ----
    const float gm = gamma[0];
    const size_t gbase = (size_t)b * CH * NPOS + m0;
    #pragma unroll
    for (int mi = 0; mi < 2; mi++) {
        const int mA = mb2 + mi * 16 + lr4;
        const int mB = mA + 8;
        const float recA = gm / (larr[mA] + larr[64 + mA]);
        const float recB = gm / (larr[mB] + larr[64 + mB]);
        #pragma unroll
        for (int cj = 0; cj < 8; cj++) {
            const int c0 = cb0 + cj * 8 + lc2;
            size_t gi0 = gbase + (size_t)c0 * NPOS;
            out[gi0 + mA]        = o[mi][cj][0] * recA + x[gi0 + mA];
            out[gi0 + NPOS + mA] = o[mi][cj][1] * recA + x[gi0 + NPOS + mA];
            out[gi0 + mB]        = o[mi][cj][2] * recB + x[gi0 + mB];
            out[gi0 + NPOS + mB] = o[mi][cj][3] * recB + x[gi0 + NPOS + mB];
        }
    }
}

// ---------------------------------------------------------------------------
extern "C" void kernel_launch(void* const* d_in, const int* in_sizes, int n_in,
                              void* d_out, int out_size)
{
    const float* x     = (const float*)d_in[0];
    const float* Wq    = (const float*)d_in[1];
    const float* bq    = (const float*)d_in[2];
    const float* Wk    = (const float*)d_in[3];
    const float* bk    = (const float*)d_in[4];
    const float* Wv    = (const float*)d_in[5];
    const float* bv    = (const float*)d_in[6];
    const float* gamma = (const float*)d_in[7];
    float* out = (float*)d_out;

    cudaFuncSetAttribute(attn_kernel, cudaFuncAttributeMaxDynamicSharedMemorySize, SM_TOTAL);

    qkv_kernel<<<dim3(128, 8), 256>>>(x, Wq, bq, Wk, bk, Wv, bv);
    attn_kernel<<<dim3(64, 8), 256, SM_TOTAL>>>(x, gamma, out);
}

// round 8
// speedup vs baseline: 1.3339x; 1.3339x over previous
#include <cuda_runtime.h>
#include <cuda_bf16.h>

#define BATCH 8
#define CH    256
#define NPOS  4096
#define IDIM  32

typedef unsigned long long u64;
typedef unsigned int u32;

__device__ __forceinline__ u64 pack2(float lo, float hi) {
    u64 r; asm("mov.b64 %0, {%1, %2};" : "=l"(r) : "f"(lo), "f"(hi)); return r;
}
__device__ __forceinline__ u64 ffma2(u64 a, u64 b, u64 c) {
    u64 d; asm("fma.rn.f32x2 %0, %1, %2, %3;" : "=l"(d) : "l"(a), "l"(b), "l"(c)); return d;
}
__device__ __forceinline__ u64 fmul2(u64 a, u64 b) {
    u64 d; asm("mul.rn.f32x2 %0, %1, %2;" : "=l"(d) : "l"(a), "l"(b)); return d;
}
__device__ __forceinline__ u64 fadd2(u64 a, u64 b) {
    u64 d; asm("add.rn.f32x2 %0, %1, %2;" : "=l"(d) : "l"(a), "l"(b)); return d;
}
__device__ __forceinline__ float2 unpack2(u64 a) {
    float2 f; asm("mov.b64 {%0, %1}, %2;" : "=f"(f.x), "=f"(f.y) : "l"(a)); return f;
}
__device__ __forceinline__ u32 bf2(float lo, float hi) {   // {lo16, hi16} packed bf16x2
    u32 r; asm("cvt.rn.bf16x2.f32 %0, %1, %2;" : "=r"(r) : "f"(hi), "f"(lo)); return r;
}
__device__ __forceinline__ u32 smem_u32(const void* p) {
    u32 a; asm("{ .reg .u64 t; cvta.to.shared.u64 t, %1; cvt.u32.u64 %0, t; }" : "=r"(a) : "l"(p));
    return a;
}
__device__ __forceinline__ void mma16816(float* d, u32 a0, u32 a1, u32 a2, u32 a3,
                                         u32 b0, u32 b1) {
    asm volatile("mma.sync.aligned.m16n8k16.row.col.f32.bf16.bf16.f32 "
                 "{%0,%1,%2,%3}, {%4,%5,%6,%7}, {%8,%9}, {%0,%1,%2,%3};"
                 : "+f"(d[0]), "+f"(d[1]), "+f"(d[2]), "+f"(d[3])
                 : "r"(a0), "r"(a1), "r"(a2), "r"(a3), "r"(b0), "r"(b1));
}
__device__ __forceinline__ void cpa16(u32 dst, const void* src) {
    asm volatile("cp.async.cg.shared.global [%0], [%1], 16;" :: "r"(dst), "l"(src));
}
__device__ __forceinline__ void cpa_commit() { asm volatile("cp.async.commit_group;" ::: "memory"); }
__device__ __forceinline__ void cpa_wait0()  { asm volatile("cp.async.wait_group 0;" ::: "memory"); }
__device__ __forceinline__ void cpa_wait1()  { asm volatile("cp.async.wait_group 1;" ::: "memory"); }

// Fast exp on the FMA pipe (no MUFU)
__device__ __forceinline__ void exp_pair(float s0, float s1, float& p0, float& p1) {
    const float MAGIC = 12582912.f;   // 1.5 * 2^23
    u64 t2  = fmul2(pack2(s0, s1), pack2(1.4426950408889634f, 1.4426950408889634f));
    u64 r2  = fadd2(t2, pack2(MAGIC, MAGIC));
    u64 rm2 = fadd2(r2, pack2(-MAGIC, -MAGIC));
    u64 f2  = ffma2(rm2, pack2(-1.f, -1.f), t2);
    u64 q2  = ffma2(f2, pack2(1.3333558146e-3f, 1.3333558146e-3f),
                        pack2(9.6181291076e-3f, 9.6181291076e-3f));
    q2 = ffma2(f2, q2, pack2(5.5504108664e-2f, 5.5504108664e-2f));
    q2 = ffma2(f2, q2, pack2(2.4022650696e-1f, 2.4022650696e-1f));
    q2 = ffma2(f2, q2, pack2(6.9314718056e-1f, 6.9314718056e-1f));
    q2 = ffma2(f2, q2, pack2(1.f, 1.f));
    float2 rr = unpack2(r2);
    float2 qq = unpack2(q2);
    int e0 = (__float_as_int(rr.x) - 0x4B400000) << 23;
    int e1 = (__float_as_int(rr.y) - 0x4B400000) << 23;
    p0 = __int_as_float(__float_as_int(qq.x) + e0);
    p1 = __int_as_float(__float_as_int(qq.y) + e1);
}

// Scratch
__device__ __nv_bfloat16 g_xhi[BATCH * NPOS * CH];    // x split, transposed [b][n][c]
__device__ __nv_bfloat16 g_xlo[BATCH * NPOS * CH];
__device__ __nv_bfloat16 g_whi[320 * CH];             // W split [320 r][256 c]
__device__ __nv_bfloat16 g_wlo[320 * CH];
__device__ __nv_bfloat16 g_qhi[BATCH * NPOS * IDIM];  // q split, [b][m][32 i]
__device__ __nv_bfloat16 g_qlo[BATCH * NPOS * IDIM];
__device__ __nv_bfloat16 g_khi[BATCH * NPOS * IDIM];
__device__ __nv_bfloat16 g_klo[BATCH * NPOS * IDIM];
__device__ __nv_bfloat16 g_v  [BATCH * CH * NPOS];    // v bf16 [b][c][n]

// ---------------------------------------------------------------------------
// Kernel 0a: x -> split bf16, transposed to [b][n][c]
// grid (64, 8), 256 threads; CTA covers 64 positions x 256 channels.
// ---------------------------------------------------------------------------
__global__ __launch_bounds__(256, 4)
void xprep_kernel(const float* __restrict__ x)
{
    const int b  = blockIdx.y;
    const int n0 = blockIdx.x * 64;
    const int tid = threadIdx.x;

    #pragma unroll
    for (int it = 0; it < 8; it++) {
        int i = tid + it * 256;               // 2048 items: 128 c-pairs x 16 n-quads
        int cp = i & 127, nq = i >> 7;
        int n = n0 + nq * 4;
        const float* p0 = x + ((size_t)b * CH + 2 * cp) * NPOS + n;
        float4 a = *(const float4*)p0;
        float4 c4 = *(const float4*)(p0 + NPOS);
        float av[4] = {a.x, a.y, a.z, a.w};
        float cv[4] = {c4.x, c4.y, c4.z, c4.w};
        #pragma unroll
        for (int e = 0; e < 4; e++) {
            float v0 = av[e], v1 = cv[e];
            u32 hw = bf2(v0, v1);
            float h0 = __int_as_float(hw << 16);
            float h1 = __int_as_float(hw & 0xFFFF0000u);
            u32 lw = bf2(v0 - h0, v1 - h1);
            size_t dst = ((size_t)b * NPOS + n + e) * CH + 2 * cp;
            *(u32*)((char*)g_xhi + dst * 2) = hw;
            *(u32*)((char*)g_xlo + dst * 2) = lw;
        }
    }
}

// ---------------------------------------------------------------------------
// Kernel 0b: W (320 x 256: 32 Wq + 32 Wk + 256 Wv) -> split bf16
// ---------------------------------------------------------------------------
__global__ __launch_bounds__(256, 4)
void wprep_kernel(const float* __restrict__ Wq, const float* __restrict__ Wk,
                  const float* __restrict__ Wv)
{
    const int gidx = blockIdx.x * 256 + threadIdx.x;   // 0..2559
    #pragma unroll
    for (int i = 0; i < 8; i++) {
        int idx4 = gidx + i * 2560;
        int el = idx4 * 4;
        int r = el >> 8, c = el & 255;
        const float* src;
        if (r < 32)       src = Wq + r * CH + c;
        else if (r < 64)  src = Wk + (r - 32) * CH + c;
        else              src = Wv + (r - 64) * CH + c;
        float4 wv = *(const float4*)src;
        u32 h0 = bf2(wv.x, wv.y);
        u32 h1 = bf2(wv.z, wv.w);
        float f0 = __int_as_float(h0 << 16),        f1 = __int_as_float(h0 & 0xFFFF0000u);
        float f2 = __int_as_float(h1 << 16),        f3 = __int_as_float(h1 & 0xFFFF0000u);
        u32 l0 = bf2(wv.x - f0, wv.y - f1);
        u32 l1 = bf2(wv.z - f2, wv.w - f3);
        *(uint2*)((char*)g_whi + (size_t)el * 2) = make_uint2(h0, h1);
        *(uint2*)((char*)g_wlo + (size_t)el * 2) = make_uint2(l0, l1);
    }
}

// ---------------------------------------------------------------------------
// Kernel 1: QKV GEMM on HMMA. grid (64, 8), 320 threads (10 warps).
// Warp w: rows w*32..w*32+31 (w<2: q/k, 3-plane split; w>=2: v, 1-plane).
// N-tile 64 positions. X tile staged via cp.async; W frags via LDG (L1).
// ---------------------------------------------------------------------------
#define GX_PITCH 528                     // 264 bf16 per row (odd multiple of 16B)
#define GXH_OFF  0                       // [64 n][528 B]
#define GXL_OFF  33792
#define GSM_TOT  67584

__global__ __launch_bounds__(320, 2)
void qkv_gemm(const float* __restrict__ bq, const float* __restrict__ bk,
              const float* __restrict__ bv)
{
    extern __shared__ char sm[];
    const u32 smb = smem_u32(sm);

    const int b    = blockIdx.y;
    const int m0   = blockIdx.x * 64;     // position tile
    const int tid  = threadIdx.x;
    const int w    = tid >> 5;
    const int lane = tid & 31;
    const int lr4  = lane >> 2;
    const int lc2  = (lane & 3) * 2;
    const int rbase = w * 32;
    const bool is_qk = (w < 2);

    // ---- Stage X tile (hi+lo), [64 n][256 c] -> pitch 528 ----
    {
        const __nv_bfloat16* xh = g_xhi + ((size_t)b * NPOS + m0) * CH;
        const __nv_bfloat16* xl = g_xlo + ((size_t)b * NPOS + m0) * CH;
        for (int i = tid; i < 4096; i += 320) {
            int plane = i >> 11;
            int row = (i >> 5) & 63;
            int seg = i & 31;
            const __nv_bfloat16* src = (plane ? xl : xh) + (size_t)row * CH + seg * 8;
            cpa16(smb + plane * 33792 + row * GX_PITCH + seg * 16, src);
        }
        cpa_commit();
        cpa_wait0();
    }
    __syncthreads();

    float d[2][8][4];
    #pragma unroll
    for (int mi = 0; mi < 2; mi++)
        #pragma unroll
        for (int nb = 0; nb < 8; nb++)
            #pragma unroll
            for (int r = 0; r < 4; r++) d[mi][nb][r] = 0.f;

    // ---- MMA: D[32 r x 64 n] = W[rows][c] * X^T ----
    const char* whb = (const char*)g_whi;
    const char* wlb = (const char*)g_wlo;
    #pragma unroll 4
    for (int ks = 0; ks < 16; ks++) {
        const int kby = ks * 32 + (lane & 3) * 4;
        u32 aH[2][4], aL[2][4];
        #pragma unroll
        for (int mi = 0; mi < 2; mi++) {
            const char* pa = whb + (size_t)(rbase + mi * 16 + lr4) * 512 + kby;
            aH[mi][0] = *(const u32*)pa;
            aH[mi][1] = *(const u32*)(pa + 4096);
            aH[mi][2] = *(const u32*)(pa + 16);
            aH[mi][3] = *(const u32*)(pa + 4096 + 16);
        }
        if (is_qk) {
            #pragma unroll
            for (int mi = 0; mi < 2; mi++) {
                const char* pa = wlb + (size_t)(rbase + mi * 16 + lr4) * 512 + kby;
                aL[mi][0] = *(const u32*)pa;
                aL[mi][1] = *(const u32*)(pa + 4096);
                aL[mi][2] = *(const u32*)(pa + 16);
                aL[mi][3] = *(const u32*)(pa + 4096 + 16);
            }
        }
        #pragma unroll
        for (int nb = 0; nb < 8; nb++) {
            const char* pb = sm + (nb * 8 + lr4) * GX_PITCH + kby;
            u32 b0 = *(const u32*)pb;
            u32 b1 = *(const u32*)(pb + 16);
            mma16816(d[0][nb], aH[0][0], aH[0][1], aH[0][2], aH[0][3], b0, b1);
            mma16816(d[1][nb], aH[1][0], aH[1][1], aH[1][2], aH[1][3], b0, b1);
            if (is_qk) {
                u32 l0 = *(const u32*)(pb + 33792);
                u32 l1 = *(const u32*)(pb + 33792 + 16);
                mma16816(d[0][nb], aH[0][0], aH[0][1], aH[0][2], aH[0][3], l0, l1);
                mma16816(d[1][nb], aH[1][0], aH[1][1], aH[1][2], aH[1][3], l0, l1);
                mma16816(d[0][nb], aL[0][0], aL[0][1], aL[0][2], aL[0][3], b0, b1);
                mma16816(d[1][nb], aL[1][0], aL[1][1], aL[1][2], aL[1][3], b0, b1);
            }
        }
    }

    // ---- v epilogue (warps 2..9): direct bf16 store with bias ----
    if (!is_qk) {
        #pragma unroll
        for (int mi = 0; mi < 2; mi++) {
            int c0 = rbase - 64 + mi * 16 + lr4;
            int c1 = c0 + 8;
            float bv0 = bv[c0], bv1 = bv[c1];
            #pragma unroll
            for (int nb = 0; nb < 8; nb++) {
                int n = m0 + nb * 8 + lc2;
                u32 w0 = bf2(d[mi][nb][0] + bv0, d[mi][nb][1] + bv0);
                u32 w1 = bf2(d[mi][nb][2] + bv1, d[mi][nb][3] + bv1);
                *(u32*)((char*)g_v + ((size_t)(b * CH + c0) * NPOS + n) * 2) = w0;
                *(u32*)((char*)g_v + ((size_t)(b * CH + c1) * NPOS + n) * 2) = w1;
            }
        }
    }

    // ---- q/k epilogue: bounce through smem (reuse X area), transpose+split ----
    __syncthreads();   // everyone done reading X
    float* bounce = (float*)sm;          // [64 n][68 r-pitch] f32
    if (is_qk) {
        #pragma unroll
        for (int mi = 0; mi < 2; mi++) {
            int r = rbase + mi * 16 + lr4;
            #pragma unroll
            for (int nb = 0; nb < 8; nb++) {
                int n = nb * 8 + lc2;
                bounce[n * 68 + r]           = d[mi][nb][0];
                bounce[(n + 1) * 68 + r]     = d[mi][nb][1];
                bounce[n * 68 + r + 8]       = d[mi][nb][2];
                bounce[(n + 1) * 68 + r + 8] = d[mi][nb][3];
            }
        }
    }
    __syncthreads();

    for (int i = tid; i < 2048; i += 320) {
        int n = i >> 5, rp = i & 31;
        float2 f = *(const float2*)(bounce + n * 68 + rp * 2);
        bool isq = (rp < 16);
        int lr = isq ? 2 * rp : 2 * rp - 32;
        float b0 = isq ? bq[lr]     : bk[lr];
        float b1 = isq ? bq[lr + 1] : bk[lr + 1];
        float v0 = f.x + b0, v1 = f.y + b1;
        u32 hw = bf2(v0, v1);
        float h0 = __int_as_float(hw << 16);
        float h1 = __int_as_float(hw & 0xFFFF0000u);
        u32 lw = bf2(v0 - h0, v1 - h1);
        size_t base = (((size_t)b * NPOS + m0 + n) * IDIM + lr) * 2;   // bytes
        if (isq) {
            *(u32*)((char*)g_qhi + base) = hw;
            *(u32*)((char*)g_qlo + base) = lw;
        } else {
            *(u32*)((char*)g_khi + base) = hw;
            *(u32*)((char*)g_klo + base) = lw;
        }
    }
}

// ---------------------------------------------------------------------------
// Kernel 2: attention (R6 version, verbatim). 512 threads, M-tile 128,
// K-chunks of 128, cp.async pipelined staging, all-HMMA.
// ---------------------------------------------------------------------------
#define LARR_OFF 0
#define QHI_OFF  1024
#define QLO_OFF  (QHI_OFF + 10240)
#define KHI0_OFF (QLO_OFF + 10240)
#define KLO0_OFF (KHI0_OFF + 10240)
#define KHI1_OFF (KLO0_OFF + 10240)
#define KLO1_OFF (KHI1_OFF + 10240)
#define P_OFF    (KLO1_OFF + 10240)
#define V_OFF    (P_OFF + 34816)
#define SM_TOTAL (V_OFF + 69632)        // 166912 B

__global__ __launch_bounds__(512, 1)
void attn_kernel(const float* __restrict__ x,
                 const float* __restrict__ gamma,
                 float* __restrict__ out)
{
    extern __shared__ char sm[];
    float* larr = (float*)(sm + LARR_OFF);
    const u32 smb = smem_u32(sm);

    const int b    = blockIdx.y;
    const int m0   = blockIdx.x * 128;
    const int tid  = threadIdx.x;
    const int w    = tid >> 5;
    const int lane = tid & 31;
    const int g    = w >> 1;
    const int h    = w & 1;
    const int lr4  = lane >> 2;
    const int lc2  = (lane & 3) * 2;

    const __nv_bfloat16* qhb = g_qhi + ((size_t)b * NPOS + m0) * IDIM;
    const __nv_bfloat16* qlb = g_qlo + ((size_t)b * NPOS + m0) * IDIM;
    const __nv_bfloat16* khb = g_khi + (size_t)b * NPOS * IDIM;
    const __nv_bfloat16* klb = g_klo + (size_t)b * NPOS * IDIM;
    const __nv_bfloat16* vb  = g_v   + (size_t)b * CH * NPOS;

    #pragma unroll
    for (int it = 0; it < 2; it++) {
        int idx = tid + it * 512;
        int j = idx & 3, row = (idx >> 2) & 127, wh = idx >> 9;
        cpa16(smb + QHI_OFF + wh * 10240 + row * 80 + j * 16,
              (wh ? qlb : qhb) + row * IDIM + j * 8);
    }
    #pragma unroll
    for (int it = 0; it < 2; it++) {
        int idx = tid + it * 512;
        int j = idx & 3, row = (idx >> 2) & 127, wh = idx >> 9;
        cpa16(smb + KHI0_OFF + wh * 10240 + row * 80 + j * 16,
              (wh ? klb : khb) + row * IDIM + j * 8);
    }
    cpa_commit();
    #pragma unroll
    for (int it = 0; it < 8; it++) {
        int idx = tid + it * 512;
        int c = idx >> 4, j = idx & 15;
        cpa16(smb + V_OFF + c * 272 + j * 16, vb + (size_t)c * NPOS + j * 8);
    }
    cpa_commit();

    float o[2][8][4];
    #pragma unroll
    for (int mi = 0; mi < 2; mi++)
        #pragma unroll
        for (int cj = 0; cj < 8; cj++)
            #pragma unroll
            for (int r = 0; r < 4; r++) o[mi][cj][r] = 0.f;
    u64 lrA2 = 0ull, lrB2 = 0ull;

    const int mb2 = (w & 3) * 32;
    const int cb0 = (w >> 2) * 64;

    for (int kk = 0; kk < NPOS / 128; kk++) {
        if (kk > 0) {
            __syncthreads();
            const int n0 = kk * 128;
            #pragma unroll
            for (int it = 0; it < 8; it++) {
                int idx = tid + it * 512;
                int c = idx >> 4, j = idx & 15;
                cpa16(smb + V_OFF + c * 272 + j * 16, vb + (size_t)c * NPOS + n0 + j * 8);
            }
            cpa_commit();
        }
        cpa_wait1();
        __syncthreads();

        const char* kh = sm + ((kk & 1) ? KHI1_OFF : KHI0_OFF);

        {
            u32 ah[2][4], al[2][4];
            #pragma unroll
            for (int ks = 0; ks < 2; ks++) {
                int kby = (ks * 16 + lc2) * 2;
                const char* pah = sm + QHI_OFF + (g * 16 + lr4) * 80 + kby;
                ah[ks][0] = *(const u32*)(pah);
                ah[ks][1] = *(const u32*)(pah + 8 * 80);
                ah[ks][2] = *(const u32*)(pah + 16);
                ah[ks][3] = *(const u32*)(pah + 8 * 80 + 16);
                al[ks][0] = *(const u32*)(pah + 10240);
                al[ks][1] = *(const u32*)(pah + 10240 + 8 * 80);
                al[ks][2] = *(const u32*)(pah + 10240 + 16);
                al[ks][3] = *(const u32*)(pah + 10240 + 8 * 80 + 16);
            }
            const int mA = g * 16 + lr4;
            #pragma unroll
            for (int nb = 0; nb < 8; nb++) {
                const int nbase = h * 64 + nb * 8;
                float d[4] = {0.f, 0.f, 0.f, 0.f};
                #pragma unroll
                for (int ks = 0; ks < 2; ks++) {
                    int kby = (ks * 16 + lc2) * 2;
                    const char* pbh = kh + (nbase + lr4) * 80 + kby;
                    u32 bh0 = *(const u32*)(pbh);
                    u32 bh1 = *(const u32*)(pbh + 16);
                    u32 bl0 = *(const u32*)(pbh + 10240);
                    u32 bl1 = *(const u32*)(pbh + 10240 + 16);
                    mma16816(d, ah[ks][0], ah[ks][1], ah[ks][2], ah[ks][3], bh0, bh1);
                    mma16816(d, ah[ks][0], ah[ks][1], ah[ks][2], ah[ks][3], bl0, bl1);
                    mma16816(d, al[ks][0], al[ks][1], al[ks][2], al[ks][3], bh0, bh1);
                }
                float pA0, pA1, pB0, pB1;
                exp_pair(d[0], d[1], pA0, pA1);
                exp_pair(d[2], d[3], pB0, pB1);
                lrA2 = fadd2(lrA2, pack2(pA0, pA1));
                lrB2 = fadd2(lrB2, pack2(pB0, pB1));
                const int c0 = nbase + lc2;
                *(u32*)(sm + P_OFF + mA * 272 + c0 * 2)       = bf2(pA0, pA1);
                *(u32*)(sm + P_OFF + (mA + 8) * 272 + c0 * 2) = bf2(pB0, pB1);
            }
        }
        __syncthreads();

        if (kk < NPOS / 128 - 1) {
            const int n1 = (kk + 1) * 128;
            const u32 kdst = smb + (((kk + 1) & 1) ? KHI1_OFF : KHI0_OFF);
            #pragma unroll
            for (int it = 0; it < 2; it++) {
                int idx = tid + it * 512;
                int j = idx & 3, row = (idx >> 2) & 127, wh = idx >> 9;
                cpa16(kdst + wh * 10240 + row * 80 + j * 16,
                      (wh ? klb : khb) + (size_t)(n1 + row) * IDIM + j * 8);
            }
            cpa_commit();
            cpa_wait1();
        } else {
            cpa_wait0();
        }
        __syncthreads();

        #pragma unroll
        for (int kstep = 0; kstep < 8; kstep++) {
            const int kby = (kstep * 16 + lc2) * 2;
            u32 a[2][4];
            #pragma unroll
            for (int mi = 0; mi < 2; mi++) {
                const char* pa = sm + P_OFF + (mb2 + mi * 16 + lr4) * 272 + kby;
                a[mi][0] = *(const u32*)(pa);
                a[mi][1] = *(const u32*)(pa + 8 * 272);
                a[mi][2] = *(const u32*)(pa + 16);
                a[mi][3] = *(const u32*)(pa + 8 * 272 + 16);
            }
            #pragma unroll
            for (int cj = 0; cj < 8; cj++) {
                const char* pb = sm + V_OFF + (cb0 + cj * 8 + lr4) * 272 + kby;
                u32 b0 = *(const u32*)(pb);
                u32 b1 = *(const u32*)(pb + 16);
                mma16816(o[0][cj], a[0][0], a[0][1], a[0][2], a[0][3], b0, b1);
                mma16816(o[1][cj], a[1][0], a[1][1], a[1][2], a[1][3], b0, b1);
            }
        }
    }

    {
        float2 fa = unpack2(lrA2);
        float2 fb = unpack2(lrB2);
        float lA = fa.x + fa.y;
        float lB = fb.x + fb.y;
        #pragma unroll
        for (int off = 1; off <= 2; off <<= 1) {
            lA += __shfl_xor_sync(0xffffffffu, lA, off);
            lB += __shfl_xor_sync(0xffffffffu, lB, off);
        }
        if ((lane & 3) == 0) {
            larr[h * 128 + g * 16 + lr4]     = lA;
            larr[h * 128 + g * 16 + lr4 + 8] = lB;
        }
    }
    __syncthreads();

    const float gm = gamma[0];
    const size_t gbase = (size_t)b * CH * NPOS + m0;
    #pragma unroll
    for (int mi = 0; mi < 2; mi++) {
        const int mA = mb2 + mi * 16 + lr4;
        const int mB = mA + 8;
        const float recA = gm / (larr[mA] + larr[128 + mA]);
        const float recB = gm / (larr[mB] + larr[128 + mB]);
        #pragma unroll
        for (int cj = 0; cj < 8; cj++) {
            const int c0 = cb0 + cj * 8 + lc2;
            size_t gi0 = gbase + (size_t)c0 * NPOS;
            out[gi0 + mA]        = o[mi][cj][0] * recA + x[gi0 + mA];
            out[gi0 + NPOS + mA] = o[mi][cj][1] * recA + x[gi0 + NPOS + mA];
            out[gi0 + mB]        = o[mi][cj][2] * recB + x[gi0 + mB];
            out[gi0 + NPOS + mB] = o[mi][cj][3] * recB + x[gi0 + NPOS + mB];
        }
    }
}

// ---------------------------------------------------------------------------
extern "C" void kernel_launch(void* const* d_in, const int* in_sizes, int n_in,
                              void* d_out, int out_size)
{
    const float* x     = (const float*)d_in[0];
    const float* Wq    = (const float*)d_in[1];
    const float* bq    = (const float*)d_in[2];
    const float* Wk    = (const float*)d_in[3];
    const float* bk    = (const float*)d_in[4];
    const float* Wv    = (const float*)d_in[5];
    const float* bv    = (const float*)d_in[6];
    const float* gamma = (const float*)d_in[7];
    float* out = (float*)d_out;

    cudaFuncSetAttribute(qkv_gemm,   cudaFuncAttributeMaxDynamicSharedMemorySize, GSM_TOT);
    cudaFuncSetAttribute(attn_kernel, cudaFuncAttributeMaxDynamicSharedMemorySize, SM_TOTAL);

    xprep_kernel<<<dim3(64, 8), 256>>>(x);
    wprep_kernel<<<10, 256>>>(Wq, Wk, Wv);
    qkv_gemm<<<dim3(64, 8), 320, GSM_TOT>>>(bq, bk, bv);
    attn_kernel<<<dim3(32, 8), 512, SM_TOTAL>>>(x, gamma, out);
}

// round 9
// speedup vs baseline: 1.3424x; 1.0064x over previous
#include <cuda_runtime.h>
#include <cuda_bf16.h>

#define BATCH 8
#define CH    256
#define NPOS  4096
#define IDIM  32

typedef unsigned long long u64;
typedef unsigned int u32;

__device__ __forceinline__ u64 pack2(float lo, float hi) {
    u64 r; asm("mov.b64 %0, {%1, %2};" : "=l"(r) : "f"(lo), "f"(hi)); return r;
}
__device__ __forceinline__ u64 ffma2(u64 a, u64 b, u64 c) {
    u64 d; asm("fma.rn.f32x2 %0, %1, %2, %3;" : "=l"(d) : "l"(a), "l"(b), "l"(c)); return d;
}
__device__ __forceinline__ u64 fmul2(u64 a, u64 b) {
    u64 d; asm("mul.rn.f32x2 %0, %1, %2;" : "=l"(d) : "l"(a), "l"(b)); return d;
}
__device__ __forceinline__ u64 fadd2(u64 a, u64 b) {
    u64 d; asm("add.rn.f32x2 %0, %1, %2;" : "=l"(d) : "l"(a), "l"(b)); return d;
}
__device__ __forceinline__ float2 unpack2(u64 a) {
    float2 f; asm("mov.b64 {%0, %1}, %2;" : "=f"(f.x), "=f"(f.y) : "l"(a)); return f;
}
__device__ __forceinline__ u32 bf2(float lo, float hi) {   // {lo16, hi16} packed bf16x2
    u32 r; asm("cvt.rn.bf16x2.f32 %0, %1, %2;" : "=r"(r) : "f"(hi), "f"(lo)); return r;
}
__device__ __forceinline__ u32 smem_u32(const void* p) {
    u32 a; asm("{ .reg .u64 t; cvta.to.shared.u64 t, %1; cvt.u32.u64 %0, t; }" : "=r"(a) : "l"(p));
    return a;
}
__device__ __forceinline__ void mma16816(float* d, u32 a0, u32 a1, u32 a2, u32 a3,
                                         u32 b0, u32 b1) {
    asm volatile("mma.sync.aligned.m16n8k16.row.col.f32.bf16.bf16.f32 "
                 "{%0,%1,%2,%3}, {%4,%5,%6,%7}, {%8,%9}, {%0,%1,%2,%3};"
                 : "+f"(d[0]), "+f"(d[1]), "+f"(d[2]), "+f"(d[3])
                 : "r"(a0), "r"(a1), "r"(a2), "r"(a3), "r"(b0), "r"(b1));
}
__device__ __forceinline__ void cpa16(u32 dst, const void* src) {
    asm volatile("cp.async.cg.shared.global [%0], [%1], 16;" :: "r"(dst), "l"(src));
}
__device__ __forceinline__ void cpa_commit() { asm volatile("cp.async.commit_group;" ::: "memory"); }
__device__ __forceinline__ void cpa_wait0()  { asm volatile("cp.async.wait_group 0;" ::: "memory"); }
__device__ __forceinline__ void cpa_wait1()  { asm volatile("cp.async.wait_group 1;" ::: "memory"); }

// Fast exp on the FMA pipe (no MUFU)
__device__ __forceinline__ void exp_pair(float s0, float s1, float& p0, float& p1) {
    const float MAGIC = 12582912.f;   // 1.5 * 2^23
    u64 t2  = fmul2(pack2(s0, s1), pack2(1.4426950408889634f, 1.4426950408889634f));
    u64 r2  = fadd2(t2, pack2(MAGIC, MAGIC));
    u64 rm2 = fadd2(r2, pack2(-MAGIC, -MAGIC));
    u64 f2  = ffma2(rm2, pack2(-1.f, -1.f), t2);
    u64 q2  = ffma2(f2, pack2(1.3333558146e-3f, 1.3333558146e-3f),
                        pack2(9.6181291076e-3f, 9.6181291076e-3f));
    q2 = ffma2(f2, q2, pack2(5.5504108664e-2f, 5.5504108664e-2f));
    q2 = ffma2(f2, q2, pack2(2.4022650696e-1f, 2.4022650696e-1f));
    q2 = ffma2(f2, q2, pack2(6.9314718056e-1f, 6.9314718056e-1f));
    q2 = ffma2(f2, q2, pack2(1.f, 1.f));
    float2 rr = unpack2(r2);
    float2 qq = unpack2(q2);
    int e0 = (__float_as_int(rr.x) - 0x4B400000) << 23;
    int e1 = (__float_as_int(rr.y) - 0x4B400000) << 23;
    p0 = __int_as_float(__float_as_int(qq.x) + e0);
    p1 = __int_as_float(__float_as_int(qq.y) + e1);
}

// Scratch
__device__ __nv_bfloat16 g_xhi[BATCH * NPOS * CH];
__device__ __nv_bfloat16 g_xlo[BATCH * NPOS * CH];
__device__ __nv_bfloat16 g_whi[320 * CH];
__device__ __nv_bfloat16 g_wlo[320 * CH];
__device__ __nv_bfloat16 g_qhi[BATCH * NPOS * IDIM];
__device__ __nv_bfloat16 g_qlo[BATCH * NPOS * IDIM];
__device__ __nv_bfloat16 g_khi[BATCH * NPOS * IDIM];
__device__ __nv_bfloat16 g_klo[BATCH * NPOS * IDIM];
__device__ __nv_bfloat16 g_v  [BATCH * CH * NPOS];

// ---------------------------------------------------------------------------
// Kernel 0a: x -> split bf16, transposed to [b][n][c]   (unchanged R8)
// ---------------------------------------------------------------------------
__global__ __launch_bounds__(256, 4)
void xprep_kernel(const float* __restrict__ x)
{
    const int b  = blockIdx.y;
    const int n0 = blockIdx.x * 64;
    const int tid = threadIdx.x;

    #pragma unroll
    for (int it = 0; it < 8; it++) {
        int i = tid + it * 256;
        int cp = i & 127, nq = i >> 7;
        int n = n0 + nq * 4;
        const float* p0 = x + ((size_t)b * CH + 2 * cp) * NPOS + n;
        float4 a = *(const float4*)p0;
        float4 c4 = *(const float4*)(p0 + NPOS);
        float av[4] = {a.x, a.y, a.z, a.w};
        float cv[4] = {c4.x, c4.y, c4.z, c4.w};
        #pragma unroll
        for (int e = 0; e < 4; e++) {
            float v0 = av[e], v1 = cv[e];
            u32 hw = bf2(v0, v1);
            float h0 = __int_as_float(hw << 16);
            float h1 = __int_as_float(hw & 0xFFFF0000u);
            u32 lw = bf2(v0 - h0, v1 - h1);
            size_t dst = ((size_t)b * NPOS + n + e) * CH + 2 * cp;
            *(u32*)((char*)g_xhi + dst * 2) = hw;
            *(u32*)((char*)g_xlo + dst * 2) = lw;
        }
    }
}

// ---------------------------------------------------------------------------
// Kernel 0b: W -> split bf16    (unchanged R8)
// ---------------------------------------------------------------------------
__global__ __launch_bounds__(256, 4)
void wprep_kernel(const float* __restrict__ Wq, const float* __restrict__ Wk,
                  const float* __restrict__ Wv)
{
    const int gidx = blockIdx.x * 256 + threadIdx.x;
    #pragma unroll
    for (int i = 0; i < 8; i++) {
        int idx4 = gidx + i * 2560;
        int el = idx4 * 4;
        int r = el >> 8, c = el & 255;
        const float* src;
        if (r < 32)       src = Wq + r * CH + c;
        else if (r < 64)  src = Wk + (r - 32) * CH + c;
        else              src = Wv + (r - 64) * CH + c;
        float4 wv = *(const float4*)src;
        u32 h0 = bf2(wv.x, wv.y);
        u32 h1 = bf2(wv.z, wv.w);
        float f0 = __int_as_float(h0 << 16),        f1 = __int_as_float(h0 & 0xFFFF0000u);
        float f2 = __int_as_float(h1 << 16),        f3 = __int_as_float(h1 & 0xFFFF0000u);
        u32 l0 = bf2(wv.x - f0, wv.y - f1);
        u32 l1 = bf2(wv.z - f2, wv.w - f3);
        *(uint2*)((char*)g_whi + (size_t)el * 2) = make_uint2(h0, h1);
        *(uint2*)((char*)g_wlo + (size_t)el * 2) = make_uint2(l0, l1);
    }
}

// ---------------------------------------------------------------------------
// Kernel 1: QKV GEMM on HMMA   (unchanged R8)
// ---------------------------------------------------------------------------
#define GX_PITCH 528
#define GSM_TOT  67584

__global__ __launch_bounds__(320, 2)
void qkv_gemm(const float* __restrict__ bq, const float* __restrict__ bk,
              const float* __restrict__ bv)
{
    extern __shared__ char sm[];
    const u32 smb = smem_u32(sm);

    const int b    = blockIdx.y;
    const int m0   = blockIdx.x * 64;
    const int tid  = threadIdx.x;
    const int w    = tid >> 5;
    const int lane = tid & 31;
    const int lr4  = lane >> 2;
    const int lc2  = (lane & 3) * 2;
    const int rbase = w * 32;
    const bool is_qk = (w < 2);

    {
        const __nv_bfloat16* xh = g_xhi + ((size_t)b * NPOS + m0) * CH;
        const __nv_bfloat16* xl = g_xlo + ((size_t)b * NPOS + m0) * CH;
        for (int i = tid; i < 4096; i += 320) {
            int plane = i >> 11;
            int row = (i >> 5) & 63;
            int seg = i & 31;
            const __nv_bfloat16* src = (plane ? xl : xh) + (size_t)row * CH + seg * 8;
            cpa16(smb + plane * 33792 + row * GX_PITCH + seg * 16, src);
        }
        cpa_commit();
        cpa_wait0();
    }
    __syncthreads();

    float d[2][8][4];
    #pragma unroll
    for (int mi = 0; mi < 2; mi++)
        #pragma unroll
        for (int nb = 0; nb < 8; nb++)
            #pragma unroll
            for (int r = 0; r < 4; r++) d[mi][nb][r] = 0.f;

    const char* whb = (const char*)g_whi;
    const char* wlb = (const char*)g_wlo;
    #pragma unroll 4
    for (int ks = 0; ks < 16; ks++) {
        const int kby = ks * 32 + (lane & 3) * 4;
        u32 aH[2][4], aL[2][4];
        #pragma unroll
        for (int mi = 0; mi < 2; mi++) {
            const char* pa = whb + (size_t)(rbase + mi * 16 + lr4) * 512 + kby;
            aH[mi][0] = *(const u32*)pa;
            aH[mi][1] = *(const u32*)(pa + 4096);
            aH[mi][2] = *(const u32*)(pa + 16);
            aH[mi][3] = *(const u32*)(pa + 4096 + 16);
        }
        if (is_qk) {
            #pragma unroll
            for (int mi = 0; mi < 2; mi++) {
                const char* pa = wlb + (size_t)(rbase + mi * 16 + lr4) * 512 + kby;
                aL[mi][0] = *(const u32*)pa;
                aL[mi][1] = *(const u32*)(pa + 4096);
                aL[mi][2] = *(const u32*)(pa + 16);
                aL[mi][3] = *(const u32*)(pa + 4096 + 16);
            }
        }
        #pragma unroll
        for (int nb = 0; nb < 8; nb++) {
            const char* pb = sm + (nb * 8 + lr4) * GX_PITCH + kby;
            u32 b0 = *(const u32*)pb;
            u32 b1 = *(const u32*)(pb + 16);
            mma16816(d[0][nb], aH[0][0], aH[0][1], aH[0][2], aH[0][3], b0, b1);
            mma16816(d[1][nb], aH[1][0], aH[1][1], aH[1][2], aH[1][3], b0, b1);
            if (is_qk) {
                u32 l0 = *(const u32*)(pb + 33792);
                u32 l1 = *(const u32*)(pb + 33792 + 16);
                mma16816(d[0][nb], aH[0][0], aH[0][1], aH[0][2], aH[0][3], l0, l1);
                mma16816(d[1][nb], aH[1][0], aH[1][1], aH[1][2], aH[1][3], l0, l1);
                mma16816(d[0][nb], aL[0][0], aL[0][1], aL[0][2], aL[0][3], b0, b1);
                mma16816(d[1][nb], aL[1][0], aL[1][1], aL[1][2], aL[1][3], b0, b1);
            }
        }
    }

    if (!is_qk) {
        #pragma unroll
        for (int mi = 0; mi < 2; mi++) {
            int c0 = rbase - 64 + mi * 16 + lr4;
            int c1 = c0 + 8;
            float bv0 = bv[c0], bv1 = bv[c1];
            #pragma unroll
            for (int nb = 0; nb < 8; nb++) {
                int n = m0 + nb * 8 + lc2;
                u32 w0 = bf2(d[mi][nb][0] + bv0, d[mi][nb][1] + bv0);
                u32 w1 = bf2(d[mi][nb][2] + bv1, d[mi][nb][3] + bv1);
                *(u32*)((char*)g_v + ((size_t)(b * CH + c0) * NPOS + n) * 2) = w0;
                *(u32*)((char*)g_v + ((size_t)(b * CH + c1) * NPOS + n) * 2) = w1;
            }
        }
    }

    __syncthreads();
    float* bounce = (float*)sm;
    if (is_qk) {
        #pragma unroll
        for (int mi = 0; mi < 2; mi++) {
            int r = rbase + mi * 16 + lr4;
            #pragma unroll
            for (int nb = 0; nb < 8; nb++) {
                int n = nb * 8 + lc2;
                bounce[n * 68 + r]           = d[mi][nb][0];
                bounce[(n + 1) * 68 + r]     = d[mi][nb][1];
                bounce[n * 68 + r + 8]       = d[mi][nb][2];
                bounce[(n + 1) * 68 + r + 8] = d[mi][nb][3];
            }
        }
    }
    __syncthreads();

    for (int i = tid; i < 2048; i += 320) {
        int n = i >> 5, rp = i & 31;
        float2 f = *(const float2*)(bounce + n * 68 + rp * 2);
        bool isq = (rp < 16);
        int lr = isq ? 2 * rp : 2 * rp - 32;
        float b0 = isq ? bq[lr]     : bk[lr];
        float b1 = isq ? bq[lr + 1] : bk[lr + 1];
        float v0 = f.x + b0, v1 = f.y + b1;
        u32 hw = bf2(v0, v1);
        float h0 = __int_as_float(hw << 16);
        float h1 = __int_as_float(hw & 0xFFFF0000u);
        u32 lw = bf2(v0 - h0, v1 - h1);
        size_t base = (((size_t)b * NPOS + m0 + n) * IDIM + lr) * 2;
        if (isq) {
            *(u32*)((char*)g_qhi + base) = hw;
            *(u32*)((char*)g_qlo + base) = lw;
        } else {
            *(u32*)((char*)g_khi + base) = hw;
            *(u32*)((char*)g_klo + base) = lw;
        }
    }
}

// ---------------------------------------------------------------------------
// Kernel 2: attention, fused-pipeline. 512 threads, M-tile 128, chunk 64 keys.
// Per iteration: PV(kk) and S(kk+1) interleaved; ONE barrier per chunk.
// P, V, K all double-buffered; Q persistent.
// ---------------------------------------------------------------------------
#define LARR_OFF 0
#define AQ_OFF   1024                    // 2 planes x [128 m][80B]      = 20480
#define AK_OFF   (AQ_OFF + 20480)        // 2 bufs x 2 planes x [64][80] = 20480
#define AP_OFF   (AK_OFF + 20480)        // 2 bufs x [128 m][144B]       = 36864
#define AV_OFF   (AP_OFF + 36864)        // 2 bufs x [256 c][144B]       = 73728
#define ASM_TOT  (AV_OFF + 73728)        // 152576 B

// PV fused step: O[32m x 64c] += P[.,16k] * V[.,16k]^T for kstep t
__device__ __forceinline__ void pv_step(const char* Pb, const char* Vb, int t,
        int mb2, int cb0, int lr4, int lc2, float (*o)[8][4])
{
    const int kby = (t * 16 + lc2) * 2;
    u32 a[2][4];
    #pragma unroll
    for (int mi = 0; mi < 2; mi++) {
        const char* pa = Pb + (mb2 + mi * 16 + lr4) * 144 + kby;
        a[mi][0] = *(const u32*)pa;
        a[mi][1] = *(const u32*)(pa + 8 * 144);
        a[mi][2] = *(const u32*)(pa + 16);
        a[mi][3] = *(const u32*)(pa + 8 * 144 + 16);
    }
    #pragma unroll
    for (int cj = 0; cj < 8; cj++) {
        const char* pb = Vb + (cb0 + cj * 8 + lr4) * 144 + kby;
        u32 b0 = *(const u32*)pb;
        u32 b1 = *(const u32*)(pb + 16);
        mma16816(o[0][cj], a[0][0], a[0][1], a[0][2], a[0][3], b0, b1);
        mma16816(o[1][cj], a[1][0], a[1][1], a[1][2], a[1][3], b0, b1);
    }
}

// S fused step: S[16q x 8n] (nb=t) -> exp -> P
__device__ __forceinline__ void s_step(const char* Kb, char* Pd, int t,
        int h, int mA, int lr4, int lc2, const u32 (*ah)[4], const u32 (*al)[4],
        u64& lrA2, u64& lrB2)
{
    const int nbase = 32 * h + t * 8;
    float d[4] = {0.f, 0.f, 0.f, 0.f};
    #pragma unroll
    for (int ks = 0; ks < 2; ks++) {
        int kby = (ks * 16 + lc2) * 2;
        const char* pbh = Kb + (nbase + lr4) * 80 + kby;
        u32 bh0 = *(const u32*)pbh;
        u32 bh1 = *(const u32*)(pbh + 16);
        u32 bl0 = *(const u32*)(pbh + 5120);
        u32 bl1 = *(const u32*)(pbh + 5120 + 16);
        mma16816(d, ah[ks][0], ah[ks][1], ah[ks][2], ah[ks][3], bh0, bh1);
        mma16816(d, ah[ks][0], ah[ks][1], ah[ks][2], ah[ks][3], bl0, bl1);
        mma16816(d, al[ks][0], al[ks][1], al[ks][2], al[ks][3], bh0, bh1);
    }
    float pA0, pA1, pB0, pB1;
    exp_pair(d[0], d[1], pA0, pA1);
    exp_pair(d[2], d[3], pB0, pB1);
    lrA2 = fadd2(lrA2, pack2(pA0, pA1));
    lrB2 = fadd2(lrB2, pack2(pB0, pB1));
    const int c0 = nbase + lc2;
    *(u32*)(Pd + mA * 144 + c0 * 2)       = bf2(pA0, pA1);
    *(u32*)(Pd + (mA + 8) * 144 + c0 * 2) = bf2(pB0, pB1);
}

__global__ __launch_bounds__(512, 1)
void attn_kernel(const float* __restrict__ x,
                 const float* __restrict__ gamma,
                 float* __restrict__ out)
{
    extern __shared__ char sm[];
    float* larr = (float*)(sm + LARR_OFF);
    const u32 smb = smem_u32(sm);

    const int b    = blockIdx.y;
    const int m0   = blockIdx.x * 128;
    const int tid  = threadIdx.x;
    const int w    = tid >> 5;
    const int lane = tid & 31;
    const int g    = w >> 1;        // S: q-group
    const int h    = w & 1;         // S: 32-key half
    const int lr4  = lane >> 2;
    const int lc2  = (lane & 3) * 2;
    const int mb2  = (w & 3) * 32;  // PV m-block
    const int cb0  = (w >> 2) * 64; // PV c-block

    const __nv_bfloat16* qhb = g_qhi + ((size_t)b * NPOS + m0) * IDIM;
    const __nv_bfloat16* qlb = g_qlo + ((size_t)b * NPOS + m0) * IDIM;
    const __nv_bfloat16* khb = g_khi + (size_t)b * NPOS * IDIM;
    const __nv_bfloat16* klb = g_klo + (size_t)b * NPOS * IDIM;
    const __nv_bfloat16* vb  = g_v   + (size_t)b * CH * NPOS;

    // ---- staging helpers (inlined) ----
    auto stage_K = [&](int buf, int n0) {
        int j = tid & 3, row = (tid >> 2) & 63, plane = tid >> 8;
        cpa16(smb + AK_OFF + buf * 10240 + plane * 5120 + row * 80 + j * 16,
              (plane ? klb : khb) + (size_t)(n0 + row) * IDIM + j * 8);
    };
    auto stage_V = [&](int buf, int n0) {
        #pragma unroll
        for (int it = 0; it < 4; it++) {
            int idx = tid + it * 512;
            int c = idx >> 3, j = idx & 7;
            cpa16(smb + AV_OFF + buf * 36864 + c * 144 + j * 16,
                  vb + (size_t)c * NPOS + n0 + j * 8);
        }
    };

    // ---- Prologue ----
    #pragma unroll
    for (int it = 0; it < 2; it++) {          // Q (1024 ops)
        int idx = tid + it * 512;
        int j = idx & 3, row = (idx >> 2) & 127, plane = idx >> 9;
        cpa16(smb + AQ_OFF + plane * 10240 + row * 80 + j * 16,
              (plane ? qlb : qhb) + (size_t)row * IDIM + j * 8);
    }
    stage_K(0, 0);
    cpa_commit();                              // G0: Q + K(0)
    stage_V(0, 0);
    stage_K(1, 64);
    cpa_commit();                              // G1: V(0) + K(1)
    cpa_wait1();                               // Q, K(0) landed
    __syncthreads();

    // Q a-frags (persistent registers)
    u32 ah[2][4], al[2][4];
    #pragma unroll
    for (int ks = 0; ks < 2; ks++) {
        int kby = (ks * 16 + lc2) * 2;
        const char* pah = sm + AQ_OFF + (g * 16 + lr4) * 80 + kby;
        ah[ks][0] = *(const u32*)(pah);
        ah[ks][1] = *(const u32*)(pah + 8 * 80);
        ah[ks][2] = *(const u32*)(pah + 16);
        ah[ks][3] = *(const u32*)(pah + 8 * 80 + 16);
        al[ks][0] = *(const u32*)(pah + 10240);
        al[ks][1] = *(const u32*)(pah + 10240 + 8 * 80);
        al[ks][2] = *(const u32*)(pah + 10240 + 16);
        al[ks][3] = *(const u32*)(pah + 10240 + 8 * 80 + 16);
    }

    float o[2][8][4];
    #pragma unroll
    for (int mi = 0; mi < 2; mi++)
        #pragma unroll
        for (int cj = 0; cj < 8; cj++)
            #pragma unroll
            for (int r = 0; r < 4; r++) o[mi][cj][r] = 0.f;
    u64 lrA2 = 0ull, lrB2 = 0ull;
    const int mA = g * 16 + lr4;

    // S(0) peeled
    #pragma unroll
    for (int t = 0; t < 4; t++)
        s_step(sm + AK_OFF, sm + AP_OFF, t, h, mA, lr4, lc2, ah, al, lrA2, lrB2);
    cpa_wait0();                               // V(0), K(1) landed
    __syncthreads();                           // P(0) visible

    // ---- Main loop: iter kk does PV(kk) + S(kk+1) ----
    #pragma unroll 1
    for (int kk = 0; kk < 63; kk++) {
        stage_V((kk + 1) & 1, (kk + 1) * 64);
        if (kk < 62) stage_K(kk & 1, (kk + 2) * 64);
        cpa_commit();

        const char* Pb = sm + AP_OFF + (kk & 1) * 18432;
        const char* Vb = sm + AV_OFF + (kk & 1) * 36864;
        const char* Kb = sm + AK_OFF + ((kk + 1) & 1) * 10240;
        char*       Pd = sm + AP_OFF + ((kk + 1) & 1) * 18432;

        #pragma unroll
        for (int t = 0; t < 4; t++) {
            pv_step(Pb, Vb, t, mb2, cb0, lr4, lc2, o);
            s_step(Kb, Pd, t, h, mA, lr4, lc2, ah, al, lrA2, lrB2);
        }
        cpa_wait0();
        __syncthreads();
    }

    // Final PV(63)
    #pragma unroll
    for (int t = 0; t < 4; t++)
        pv_step(sm + AP_OFF + 18432, sm + AV_OFF + 36864, t, mb2, cb0, lr4, lc2, o);

    // ---- l reduction ----
    {
        float2 fa = unpack2(lrA2);
        float2 fb = unpack2(lrB2);
        float lA = fa.x + fa.y;
        float lB = fb.x + fb.y;
        #pragma unroll
        for (int off = 1; off <= 2; off <<= 1) {
            lA += __shfl_xor_sync(0xffffffffu, lA, off);
            lB += __shfl_xor_sync(0xffffffffu, lB, off);
        }
        if ((lane & 3) == 0) {
            larr[h * 128 + g * 16 + lr4]     = lA;
            larr[h * 128 + g * 16 + lr4 + 8] = lB;
        }
    }
    __syncthreads();

    // ---- Epilogue ----
    const float gm = gamma[0];
    const size_t gbase = (size_t)b * CH * NPOS + m0;
    #pragma unroll
    for (int mi = 0; mi < 2; mi++) {
        const int mAe = mb2 + mi * 16 + lr4;
        const int mBe = mAe + 8;
        const float recA = gm / (larr[mAe] + larr[128 + mAe]);
        const float recB = gm / (larr[mBe] + larr[128 + mBe]);
        #pragma unroll
        for (int cj = 0; cj < 8; cj++) {
            const int c0 = cb0 + cj * 8 + lc2;
            size_t gi0 = gbase + (size_t)c0 * NPOS;
            out[gi0 + mAe]        = o[mi][cj][0] * recA + x[gi0 + mAe];
            out[gi0 + NPOS + mAe] = o[mi][cj][1] * recA + x[gi0 + NPOS + mAe];
            out[gi0 + mBe]        = o[mi][cj][2] * recB + x[gi0 + mBe];
            out[gi0 + NPOS + mBe] = o[mi][cj][3] * recB + x[gi0 + NPOS + mBe];
        }
    }
}

// ---------------------------------------------------------------------------
extern "C" void kernel_launch(void* const* d_in, const int* in_sizes, int n_in,
                              void* d_out, int out_size)
{
    const float* x     = (const float*)d_in[0];
    const float* Wq    = (const float*)d_in[1];
    const float* bq    = (const float*)d_in[2];
    const float* Wk    = (const float*)d_in[3];
    const float* bk    = (const float*)d_in[4];
    const float* Wv    = (const float*)d_in[5];
    const float* bv    = (const float*)d_in[6];
    const float* gamma = (const float*)d_in[7];
    float* out = (float*)d_out;

    cudaFuncSetAttribute(qkv_gemm,    cudaFuncAttributeMaxDynamicSharedMemorySize, GSM_TOT);
    cudaFuncSetAttribute(attn_kernel, cudaFuncAttributeMaxDynamicSharedMemorySize, ASM_TOT);

    xprep_kernel<<<dim3(64, 8), 256>>>(x);
    wprep_kernel<<<10, 256>>>(Wq, Wk, Wv);
    qkv_gemm<<<dim3(64, 8), 320, GSM_TOT>>>(bq, bk, bv);
    attn_kernel<<<dim3(32, 8), 512, ASM_TOT>>>(x, gamma, out);
}